// round 8
// baseline (speedup 1.0000x reference)
#include <cuda_runtime.h>
#include <cuda_fp16.h>
#include <math.h>

#define N_NODES 50000
#define F_IN    50
#define H1      128
#define H2      64
#define E_MAX   1700000
#define SCAN_B  256
#define NBLK    ((N_NODES + SCAN_B - 1) / SCAN_B)   // 196

// ---- scratch (__device__ globals; no allocations allowed) ----
__device__ __align__(16) __half g_Hh[N_NODES * H1];   // h' = dinv * (x @ W_gcn), fp16
__device__ int   g_deg[N_NODES];                      // re-zeroed at end of k_scan3
__device__ float g_dinv[N_NODES];
__device__ int   g_rowptr[N_NODES + 1];
__device__ int   g_cursor[N_NODES];
__device__ int   g_csrc[E_MAX];
__device__ int   g_bsum[NBLK];
__device__ int   g_boff[NBLK];
__device__ float g_colsum[H1];                        // re-zeroed at end of k_final

// ---------------------------------------------------------------------------
// 1) in-degree histogram at dst, int4-vectorized (edge_index is int32)
__global__ void k_deg(const int* __restrict__ ei, int E) {
    int i = blockIdx.x * blockDim.x + threadIdx.x;
    int nv = E >> 2;
    const int4* d4 = (const int4*)(ei + E);
    if (i < nv) {
        int4 d = d4[i];
        atomicAdd(&g_deg[d.x], 1);
        atomicAdd(&g_deg[d.y], 1);
        atomicAdd(&g_deg[d.z], 1);
        atomicAdd(&g_deg[d.w], 1);
    } else if (i == nv) {
        for (int r = nv << 2; r < E; r++) atomicAdd(&g_deg[ei[E + r]], 1);
    }
}

// 2a) per-block partial sums of deg
__global__ void k_scan1() {
    __shared__ int ws[8];
    int i = blockIdx.x * SCAN_B + threadIdx.x;
    int v = (i < N_NODES) ? g_deg[i] : 0;
    int lane = threadIdx.x & 31, wid = threadIdx.x >> 5;
    #pragma unroll
    for (int o = 16; o > 0; o >>= 1) v += __shfl_down_sync(0xffffffffu, v, o);
    if (lane == 0) ws[wid] = v;
    __syncthreads();
    if (threadIdx.x == 0) {
        int s = 0;
        #pragma unroll
        for (int w = 0; w < 8; w++) s += ws[w];
        g_bsum[blockIdx.x] = s;
    }
}

// 2b) one small block: exclusive scan of the 196 block sums
__global__ void k_scan2() {
    __shared__ int ws[8];
    int tid = threadIdx.x;           // 256 threads
    int v = (tid < NBLK) ? g_bsum[tid] : 0;
    int lane = tid & 31, wid = tid >> 5;
    int x = v;
    #pragma unroll
    for (int o = 1; o < 32; o <<= 1) {
        int y = __shfl_up_sync(0xffffffffu, x, o);
        if (lane >= o) x += y;
    }
    if (lane == 31) ws[wid] = x;
    __syncthreads();
    if (wid == 0 && lane < 8) {
        int w = ws[lane];
        #pragma unroll
        for (int o = 1; o < 8; o <<= 1) {
            int y = __shfl_up_sync(0xffu, w, o);
            if (lane >= o) w += y;
        }
        ws[lane] = w;
    }
    __syncthreads();
    int off = (wid > 0) ? ws[wid - 1] : 0;
    int excl = off + x - v;
    if (tid < NBLK) g_boff[tid] = excl;
    if (tid == NBLK - 1) g_rowptr[N_NODES] = excl + v;
}

// 2c) apply offsets -> rowptr/cursor; fused dinv; re-zero deg for next replay
__global__ void k_scan3() {
    __shared__ int ws[8];
    int i = blockIdx.x * SCAN_B + threadIdx.x;
    int v = (i < N_NODES) ? g_deg[i] : 0;
    int lane = threadIdx.x & 31, wid = threadIdx.x >> 5;
    int x = v;
    #pragma unroll
    for (int o = 1; o < 32; o <<= 1) {
        int y = __shfl_up_sync(0xffffffffu, x, o);
        if (lane >= o) x += y;
    }
    if (lane == 31) ws[wid] = x;
    __syncthreads();
    if (wid == 0 && lane < 8) {
        int w = ws[lane];
        #pragma unroll
        for (int o = 1; o < 8; o <<= 1) {
            int y = __shfl_up_sync(0xffu, w, o);
            if (lane >= o) w += y;
        }
        ws[lane] = w;
    }
    __syncthreads();
    int woff = (wid > 0) ? ws[wid - 1] : 0;
    if (i < N_NODES) {
        int p = g_boff[blockIdx.x] + woff + x - v;
        g_rowptr[i] = p;
        g_cursor[i] = p;
        g_dinv[i] = rsqrtf((float)(v + 1));
        g_deg[i] = 0;                 // ready for next call
    }
}

// 3) fill CSR, int4-vectorized index loads
__global__ void k_fill(const int* __restrict__ ei, int E) {
    int i = blockIdx.x * blockDim.x + threadIdx.x;
    int nv = E >> 2;
    const int4* s4 = (const int4*)ei;
    const int4* d4 = (const int4*)(ei + E);
    if (i < nv) {
        int4 s = s4[i];
        int4 d = d4[i];
        g_csrc[atomicAdd(&g_cursor[d.x], 1)] = s.x;
        g_csrc[atomicAdd(&g_cursor[d.y], 1)] = s.y;
        g_csrc[atomicAdd(&g_cursor[d.z], 1)] = s.z;
        g_csrc[atomicAdd(&g_cursor[d.w], 1)] = s.w;
    } else if (i == nv) {
        for (int r = nv << 2; r < E; r++)
            g_csrc[atomicAdd(&g_cursor[ei[E + r]], 1)] = ei[r];
    }
}

// 4) h = x @ W_gcn, fp16 out (unscaled; k_scale applies dinv afterwards)
#define GN 32
__global__ void k_gemm(const float* __restrict__ x, const float* __restrict__ W) {
    __shared__ float sW[F_IN * H1];
    __shared__ float sx[GN * F_IN];
    int t = threadIdx.x;              // 0..63
    for (int i = t; i < F_IN * H1; i += 64) sW[i] = W[i];
    int node0 = blockIdx.x * GN;
    int nl = min(GN, N_NODES - node0);
    for (int i = t; i < nl * F_IN; i += 64) sx[i] = x[node0 * F_IN + i];
    __syncthreads();

    int c = 2 * t;
    __half2* Hh2 = (__half2*)g_Hh;
    for (int n = 0; n < nl; n += 4) {
        float2 a0 = {0.f, 0.f}, a1 = {0.f, 0.f}, a2 = {0.f, 0.f}, a3 = {0.f, 0.f};
        #pragma unroll
        for (int k = 0; k < F_IN; k++) {
            float w0 = sW[k * H1 + c], w1 = sW[k * H1 + c + 1];
            float x0 = sx[(n + 0) * F_IN + k];
            float x1 = sx[(n + 1) * F_IN + k];
            float x2 = sx[(n + 2) * F_IN + k];
            float x3 = sx[(n + 3) * F_IN + k];
            a0.x = fmaf(x0, w0, a0.x); a0.y = fmaf(x0, w1, a0.y);
            a1.x = fmaf(x1, w0, a1.x); a1.y = fmaf(x1, w1, a1.y);
            a2.x = fmaf(x2, w0, a2.x); a2.y = fmaf(x2, w1, a2.y);
            a3.x = fmaf(x3, w0, a3.x); a3.y = fmaf(x3, w1, a3.y);
        }
        int v = node0 + n;
        Hh2[(v + 0) * 64 + t] = __float22half2_rn(a0);
        Hh2[(v + 1) * 64 + t] = __float22half2_rn(a1);
        Hh2[(v + 2) * 64 + t] = __float22half2_rn(a2);
        Hh2[(v + 3) * 64 + t] = __float22half2_rn(a3);
    }
}

// 4b) in-place scale: h' = dinv * h  (runs after gemm AND scan3)
__global__ void k_scale() {
    int i = blockIdx.x * blockDim.x + threadIdx.x;   // over N_NODES*32 uint2
    if (i < N_NODES * 32) {
        int v = i >> 5;
        float dv = g_dinv[v];
        uint2* q = (uint2*)g_Hh;
        uint2 m = q[i];
        float2 f0 = __half22float2(*(__half2*)&m.x);
        float2 f1 = __half22float2(*(__half2*)&m.y);
        f0.x *= dv; f0.y *= dv; f1.x *= dv; f1.y *= dv;
        *(__half2*)&m.x = __float22half2_rn(f0);
        *(__half2*)&m.y = __float22half2_rn(f1);
        q[i] = m;
    }
}

// 5) warp-per-node aggregate: acc = h'[v] + sum h'[src]; out = dv*acc (+b, relu)
//    lane covers 4 features (uint2 = 2 half2). 4 warps/block, 8 nodes/warp.
#define AGG_W   4
#define AGG_NPW 8
__global__ void k_agg(const float* __restrict__ b) {
    int lane = threadIdx.x & 31, w = threadIdx.x >> 5;
    int node0 = (blockIdx.x * AGG_W + w) * AGG_NPW;
    const uint2* __restrict__ Hp = (const uint2*)g_Hh;   // 32 uint2 per row
    int f = lane * 4;
    float b0 = b[f], b1 = b[f + 1], b2 = b[f + 2], b3 = b[f + 3];
    float s0 = 0.f, s1 = 0.f, s2 = 0.f, s3 = 0.f;

    int nend = min(AGG_NPW, N_NODES - node0);
    for (int n = 0; n < nend; n++) {
        int v = node0 + n;
        float dv = g_dinv[v];
        uint2 hm = Hp[v * 32 + lane];                    // self (already dinv-scaled)
        float2 h0 = __half22float2(*(__half2*)&hm.x);
        float2 h1 = __half22float2(*(__half2*)&hm.y);
        float a0 = h0.x, a1 = h0.y, a2 = h1.x, a3 = h1.y;

        int e = g_rowptr[v], end = g_rowptr[v + 1];
        for (; e + 3 < end; e += 4) {
            int i0 = g_csrc[e],     i1 = g_csrc[e + 1];
            int i2 = g_csrc[e + 2], i3 = g_csrc[e + 3];
            uint2 m0 = Hp[i0 * 32 + lane];
            uint2 m1 = Hp[i1 * 32 + lane];
            uint2 m2 = Hp[i2 * 32 + lane];
            uint2 m3 = Hp[i3 * 32 + lane];
            float2 p0 = __half22float2(*(__half2*)&m0.x), q0 = __half22float2(*(__half2*)&m0.y);
            float2 p1 = __half22float2(*(__half2*)&m1.x), q1 = __half22float2(*(__half2*)&m1.y);
            float2 p2 = __half22float2(*(__half2*)&m2.x), q2 = __half22float2(*(__half2*)&m2.y);
            float2 p3 = __half22float2(*(__half2*)&m3.x), q3 = __half22float2(*(__half2*)&m3.y);
            a0 += p0.x + p1.x + p2.x + p3.x;
            a1 += p0.y + p1.y + p2.y + p3.y;
            a2 += q0.x + q1.x + q2.x + q3.x;
            a3 += q0.y + q1.y + q2.y + q3.y;
        }
        for (; e < end; e++) {
            int i0 = g_csrc[e];
            uint2 m0 = Hp[i0 * 32 + lane];
            float2 p0 = __half22float2(*(__half2*)&m0.x), q0 = __half22float2(*(__half2*)&m0.y);
            a0 += p0.x; a1 += p0.y; a2 += q0.x; a3 += q0.y;
        }
        s0 += fmaxf(fmaf(dv, a0, b0), 0.f);
        s1 += fmaxf(fmaf(dv, a1, b1), 0.f);
        s2 += fmaxf(fmaf(dv, a2, b2), 0.f);
        s3 += fmaxf(fmaf(dv, a3, b3), 0.f);
    }
    atomicAdd(&g_colsum[f],     s0);
    atomicAdd(&g_colsum[f + 1], s1);
    atomicAdd(&g_colsum[f + 2], s2);
    atomicAdd(&g_colsum[f + 3], s3);
}

// 6) emb = tanh( mean @ W_lin + b_lin ); re-zero colsum for next replay
__global__ void k_final(const float* __restrict__ Wl, const float* __restrict__ bl,
                        float* __restrict__ out) {
    __shared__ float mean[H1];
    int t = threadIdx.x; // 0..63
    mean[t]      = g_colsum[t]      * (1.0f / (float)N_NODES);
    mean[t + 64] = g_colsum[t + 64] * (1.0f / (float)N_NODES);
    g_colsum[t] = 0.0f;
    g_colsum[t + 64] = 0.0f;
    __syncthreads();
    float acc = bl[t];
    #pragma unroll 8
    for (int k = 0; k < H1; k++)
        acc = fmaf(mean[k], Wl[k * H2 + t], acc);
    out[t] = tanhf(acc);
}

// ---------------------------------------------------------------------------
extern "C" void kernel_launch(void* const* d_in, const int* in_sizes, int n_in,
                              void* d_out, int out_size) {
    const float* x  = (const float*)d_in[0];
    const float* Wg = (const float*)d_in[1];
    const float* bg = (const float*)d_in[2];
    const float* Wl = (const float*)d_in[3];
    const float* bl = (const float*)d_in[4];
    const int*   ei = (const int*)d_in[5];
    int E = in_sizes[5] / 2;
    float* out = (float*)d_out;

    // one-time host-side infra (outside capture on first call)
    static cudaStream_t s_side = nullptr;
    static cudaEvent_t  s_ev_fork = nullptr, s_ev_scan = nullptr, s_ev_join = nullptr;
    if (s_side == nullptr) {
        cudaStreamCreateWithFlags(&s_side, cudaStreamNonBlocking);
        cudaEventCreateWithFlags(&s_ev_fork, cudaEventDisableTiming);
        cudaEventCreateWithFlags(&s_ev_scan, cudaEventDisableTiming);
        cudaEventCreateWithFlags(&s_ev_join, cudaEventDisableTiming);
    }

    // fork: gemm (x, W only) on side stream
    cudaEventRecord(s_ev_fork, 0);
    cudaStreamWaitEvent(s_side, s_ev_fork, 0);
    k_gemm<<<(N_NODES + GN - 1) / GN, 64, 0, s_side>>>(x, Wg);

    // main: CSR build chain
    {
        int nv = E / 4 + 1;
        k_deg<<<(nv + 255) / 256, 256>>>(ei, E);
    }
    k_scan1<<<NBLK, SCAN_B>>>();
    k_scan2<<<1, 256>>>();
    k_scan3<<<NBLK, SCAN_B>>>();
    cudaEventRecord(s_ev_scan, 0);

    // side: scale needs gemm (program order on s_side) AND dinv (scan3)
    cudaStreamWaitEvent(s_side, s_ev_scan, 0);
    k_scale<<<(N_NODES * 32 + 255) / 256, 256, 0, s_side>>>();
    cudaEventRecord(s_ev_join, s_side);

    // main: fill runs concurrently with gemm/scale
    {
        int nv = E / 4 + 1;
        k_fill<<<(nv + 255) / 256, 256>>>(ei, E);
    }

    // join: agg needs h' (side) and CSR (main)
    cudaStreamWaitEvent(0, s_ev_join, 0);
    k_agg<<<(N_NODES + AGG_W * AGG_NPW - 1) / (AGG_W * AGG_NPW), AGG_W * 32>>>(bg);
    k_final<<<1, H2>>>(Wl, bl, out);
}

// round 9
// speedup vs baseline: 1.5785x; 1.5785x over previous
#include <cuda_runtime.h>
#include <cuda_fp16.h>
#include <math.h>

#define N_NODES 50000
#define F_IN    50
#define H1      128
#define H2      64
#define E_MAX   1700000
#define SCAN_B  256
#define NBLK    ((N_NODES + SCAN_B - 1) / SCAN_B)   // 196

// ---- scratch (__device__ globals; no allocations allowed) ----
__device__ __align__(16) __half g_Hh[N_NODES * H1];   // h' = dinv * (x @ W_gcn), fp16
__device__ int   g_deg[N_NODES];                      // re-zeroed at end of k_scan3
__device__ float g_dinv[N_NODES];
__device__ int   g_rowptr[N_NODES + 1];
__device__ int   g_cursor[N_NODES];
__device__ int   g_csrc[E_MAX];
__device__ int   g_bsum[NBLK];
__device__ int   g_boff[NBLK];
__device__ float g_colsum[H1];                        // re-zeroed at end of k_final

// ---------------------------------------------------------------------------
// 1) in-degree histogram at dst (edge_index is int32; g_deg pre-zeroed)
__global__ void k_deg(const int* __restrict__ ei, int E) {
    int i = blockIdx.x * blockDim.x + threadIdx.x;
    if (i < E) atomicAdd(&g_deg[ei[E + i]], 1);
}

// 2a) per-block partial sums of deg
__global__ void k_scan1() {
    __shared__ int ws[8];
    int i = blockIdx.x * SCAN_B + threadIdx.x;
    int v = (i < N_NODES) ? g_deg[i] : 0;
    int lane = threadIdx.x & 31, wid = threadIdx.x >> 5;
    #pragma unroll
    for (int o = 16; o > 0; o >>= 1) v += __shfl_down_sync(0xffffffffu, v, o);
    if (lane == 0) ws[wid] = v;
    __syncthreads();
    if (threadIdx.x == 0) {
        int s = 0;
        #pragma unroll
        for (int w = 0; w < 8; w++) s += ws[w];
        g_bsum[blockIdx.x] = s;
    }
}

// 2b) one small block: exclusive scan of the 196 block sums
__global__ void k_scan2() {
    __shared__ int ws[8];
    int tid = threadIdx.x;           // 256 threads
    int v = (tid < NBLK) ? g_bsum[tid] : 0;
    int lane = tid & 31, wid = tid >> 5;
    int x = v;
    #pragma unroll
    for (int o = 1; o < 32; o <<= 1) {
        int y = __shfl_up_sync(0xffffffffu, x, o);
        if (lane >= o) x += y;
    }
    if (lane == 31) ws[wid] = x;
    __syncthreads();
    if (wid == 0 && lane < 8) {
        int w = ws[lane];
        #pragma unroll
        for (int o = 1; o < 8; o <<= 1) {
            int y = __shfl_up_sync(0xffu, w, o);
            if (lane >= o) w += y;
        }
        ws[lane] = w;
    }
    __syncthreads();
    int off = (wid > 0) ? ws[wid - 1] : 0;
    int excl = off + x - v;
    if (tid < NBLK) g_boff[tid] = excl;
    if (tid == NBLK - 1) g_rowptr[N_NODES] = excl + v;
}

// 2c) apply offsets -> rowptr/cursor; fused dinv; re-zero deg for next replay
__global__ void k_scan3() {
    __shared__ int ws[8];
    int i = blockIdx.x * SCAN_B + threadIdx.x;
    int v = (i < N_NODES) ? g_deg[i] : 0;
    int lane = threadIdx.x & 31, wid = threadIdx.x >> 5;
    int x = v;
    #pragma unroll
    for (int o = 1; o < 32; o <<= 1) {
        int y = __shfl_up_sync(0xffffffffu, x, o);
        if (lane >= o) x += y;
    }
    if (lane == 31) ws[wid] = x;
    __syncthreads();
    if (wid == 0 && lane < 8) {
        int w = ws[lane];
        #pragma unroll
        for (int o = 1; o < 8; o <<= 1) {
            int y = __shfl_up_sync(0xffu, w, o);
            if (lane >= o) w += y;
        }
        ws[lane] = w;
    }
    __syncthreads();
    int woff = (wid > 0) ? ws[wid - 1] : 0;
    if (i < N_NODES) {
        int p = g_boff[blockIdx.x] + woff + x - v;
        g_rowptr[i] = p;
        g_cursor[i] = p;
        g_dinv[i] = rsqrtf((float)(v + 1));
        g_deg[i] = 0;                 // ready for next call
    }
}

// 3) fill CSR: group srcs by dst
__global__ void k_fill(const int* __restrict__ ei, int E) {
    int i = blockIdx.x * blockDim.x + threadIdx.x;
    if (i < E) {
        int src = ei[i];
        int dst = ei[E + i];
        int pos = atomicAdd(&g_cursor[dst], 1);
        g_csrc[pos] = src;
    }
}

// 4) h = x @ W_gcn, fp16 out (unscaled; k_scale applies dinv afterwards)
#define GN 32
__global__ void k_gemm(const float* __restrict__ x, const float* __restrict__ W) {
    __shared__ float sW[F_IN * H1];
    __shared__ float sx[GN * F_IN];
    int t = threadIdx.x;              // 0..63
    for (int i = t; i < F_IN * H1; i += 64) sW[i] = W[i];
    int node0 = blockIdx.x * GN;
    int nl = min(GN, N_NODES - node0);
    for (int i = t; i < nl * F_IN; i += 64) sx[i] = x[node0 * F_IN + i];
    __syncthreads();

    int c = 2 * t;
    __half2* Hh2 = (__half2*)g_Hh;
    for (int n = 0; n < nl; n += 4) {
        float2 a0 = {0.f, 0.f}, a1 = {0.f, 0.f}, a2 = {0.f, 0.f}, a3 = {0.f, 0.f};
        #pragma unroll
        for (int k = 0; k < F_IN; k++) {
            float w0 = sW[k * H1 + c], w1 = sW[k * H1 + c + 1];
            float x0 = sx[(n + 0) * F_IN + k];
            float x1 = sx[(n + 1) * F_IN + k];
            float x2 = sx[(n + 2) * F_IN + k];
            float x3 = sx[(n + 3) * F_IN + k];
            a0.x = fmaf(x0, w0, a0.x); a0.y = fmaf(x0, w1, a0.y);
            a1.x = fmaf(x1, w0, a1.x); a1.y = fmaf(x1, w1, a1.y);
            a2.x = fmaf(x2, w0, a2.x); a2.y = fmaf(x2, w1, a2.y);
            a3.x = fmaf(x3, w0, a3.x); a3.y = fmaf(x3, w1, a3.y);
        }
        int v = node0 + n;
        Hh2[(v + 0) * 64 + t] = __float22half2_rn(a0);
        Hh2[(v + 1) * 64 + t] = __float22half2_rn(a1);
        Hh2[(v + 2) * 64 + t] = __float22half2_rn(a2);
        Hh2[(v + 3) * 64 + t] = __float22half2_rn(a3);
    }
}

// 4b) in-place scale: h' = dinv * h  (after gemm AND scan3)
__global__ void k_scale() {
    int i = blockIdx.x * blockDim.x + threadIdx.x;   // over N_NODES*32 uint2
    if (i < N_NODES * 32) {
        int v = i >> 5;
        float dv = g_dinv[v];
        uint2* q = (uint2*)g_Hh;
        uint2 m = q[i];
        float2 f0 = __half22float2(*(__half2*)&m.x);
        float2 f1 = __half22float2(*(__half2*)&m.y);
        f0.x *= dv; f0.y *= dv; f1.x *= dv; f1.y *= dv;
        *(__half2*)&m.x = __float22half2_rn(f0);
        *(__half2*)&m.y = __float22half2_rn(f1);
        q[i] = m;
    }
}

// 5) dst-centric aggregate (R7 shape: 64 thr, 4B/lane, broadcast idx loads),
//    prescaled features -> no per-edge dinv load; x8 unroll for MLP.
//    out[v] = dv*(h'[v] + sum h'[src]) + b, relu, colsum.
#define AGG_NODES 16
__global__ void k_agg(const float* __restrict__ b) {
    int t = threadIdx.x;              // 0..63, feature pair (2t, 2t+1)
    int node0 = blockIdx.x * AGG_NODES;
    const __half2* __restrict__ Hh2 = (const __half2*)g_Hh;
    float bx = b[2 * t], by = b[2 * t + 1];
    float sx = 0.f, sy = 0.f;

    int nend = min(AGG_NODES, N_NODES - node0);
    for (int n = 0; n < nend; n++) {
        int v = node0 + n;
        float dv = g_dinv[v];
        float2 hv = __half22float2(Hh2[v * 64 + t]);
        float ax = hv.x, ay = hv.y;

        int e = g_rowptr[v], end = g_rowptr[v + 1];
        for (; e + 7 < end; e += 8) {
            int i0 = g_csrc[e],     i1 = g_csrc[e + 1];
            int i2 = g_csrc[e + 2], i3 = g_csrc[e + 3];
            int i4 = g_csrc[e + 4], i5 = g_csrc[e + 5];
            int i6 = g_csrc[e + 6], i7 = g_csrc[e + 7];
            float2 m0 = __half22float2(Hh2[i0 * 64 + t]);
            float2 m1 = __half22float2(Hh2[i1 * 64 + t]);
            float2 m2 = __half22float2(Hh2[i2 * 64 + t]);
            float2 m3 = __half22float2(Hh2[i3 * 64 + t]);
            float2 m4 = __half22float2(Hh2[i4 * 64 + t]);
            float2 m5 = __half22float2(Hh2[i5 * 64 + t]);
            float2 m6 = __half22float2(Hh2[i6 * 64 + t]);
            float2 m7 = __half22float2(Hh2[i7 * 64 + t]);
            ax += (m0.x + m1.x) + (m2.x + m3.x) + (m4.x + m5.x) + (m6.x + m7.x);
            ay += (m0.y + m1.y) + (m2.y + m3.y) + (m4.y + m5.y) + (m6.y + m7.y);
        }
        for (; e < end; e++) {
            int i0 = g_csrc[e];
            float2 m0 = __half22float2(Hh2[i0 * 64 + t]);
            ax += m0.x; ay += m0.y;
        }
        sx += fmaxf(fmaf(dv, ax, bx), 0.f);
        sy += fmaxf(fmaf(dv, ay, by), 0.f);
    }
    atomicAdd(&g_colsum[2 * t], sx);
    atomicAdd(&g_colsum[2 * t + 1], sy);
}

// 6) emb = tanh( mean @ W_lin + b_lin ); re-zero colsum for next replay
__global__ void k_final(const float* __restrict__ Wl, const float* __restrict__ bl,
                        float* __restrict__ out) {
    __shared__ float mean[H1];
    int t = threadIdx.x; // 0..63
    mean[t]      = g_colsum[t]      * (1.0f / (float)N_NODES);
    mean[t + 64] = g_colsum[t + 64] * (1.0f / (float)N_NODES);
    g_colsum[t] = 0.0f;
    g_colsum[t + 64] = 0.0f;
    __syncthreads();
    float acc = bl[t];
    #pragma unroll 8
    for (int k = 0; k < H1; k++)
        acc = fmaf(mean[k], Wl[k * H2 + t], acc);
    out[t] = tanhf(acc);
}

// ---------------------------------------------------------------------------
extern "C" void kernel_launch(void* const* d_in, const int* in_sizes, int n_in,
                              void* d_out, int out_size) {
    const float* x  = (const float*)d_in[0];
    const float* Wg = (const float*)d_in[1];
    const float* bg = (const float*)d_in[2];
    const float* Wl = (const float*)d_in[3];
    const float* bl = (const float*)d_in[4];
    const int*   ei = (const int*)d_in[5];
    int E = in_sizes[5] / 2;
    float* out = (float*)d_out;

    // one-time host-side infra (outside capture on first call)
    static cudaStream_t s_side = nullptr;
    static cudaEvent_t  s_ev_fork = nullptr, s_ev_scan = nullptr, s_ev_join = nullptr;
    if (s_side == nullptr) {
        cudaStreamCreateWithFlags(&s_side, cudaStreamNonBlocking);
        cudaEventCreateWithFlags(&s_ev_fork, cudaEventDisableTiming);
        cudaEventCreateWithFlags(&s_ev_scan, cudaEventDisableTiming);
        cudaEventCreateWithFlags(&s_ev_join, cudaEventDisableTiming);
    }

    // fork: gemm (x, W only) on side stream
    cudaEventRecord(s_ev_fork, 0);
    cudaStreamWaitEvent(s_side, s_ev_fork, 0);
    k_gemm<<<(N_NODES + GN - 1) / GN, 64, 0, s_side>>>(x, Wg);

    // main: CSR build chain
    k_deg<<<(E + 255) / 256, 256>>>(ei, E);
    k_scan1<<<NBLK, SCAN_B>>>();
    k_scan2<<<1, 256>>>();
    k_scan3<<<NBLK, SCAN_B>>>();
    cudaEventRecord(s_ev_scan, 0);

    // side: scale needs gemm (program order) AND dinv (scan3)
    cudaStreamWaitEvent(s_side, s_ev_scan, 0);
    k_scale<<<(N_NODES * 32 + 255) / 256, 256, 0, s_side>>>();
    cudaEventRecord(s_ev_join, s_side);

    // main: fill runs concurrently with gemm/scale
    k_fill<<<(E + 255) / 256, 256>>>(ei, E);

    // join: agg needs h' (side) and CSR (main)
    cudaStreamWaitEvent(0, s_ev_join, 0);
    k_agg<<<(N_NODES + AGG_NODES - 1) / AGG_NODES, 64>>>(bg);
    k_final<<<1, H2>>>(Wl, bl, out);
}